// round 6
// baseline (speedup 1.0000x reference)
#include <cuda_runtime.h>
#include <math.h>
#include <stdint.h>

// ---------------------------------------------------------------------------
// Problem dims
// ---------------------------------------------------------------------------
namespace {
constexpr int B_   = 16;
constexpr int L_   = 512;
constexpr int N_   = 321;
constexpr int MK_  = 4;
constexpr int D_   = 512;
constexpr int S_   = 16;
constexpr int DTR_ = 32;
constexpr int PRED_= 96;
constexpr int T_   = N_ + MK_;        // 325
constexpr int MROWS = B_ * T_;        // 5200
constexpr int NC_  = 13;              // scan chunks
constexpr int CH_  = 25;              // steps per chunk (13*25 = 325)
}

// ---------------------------------------------------------------------------
// Scratch
// ---------------------------------------------------------------------------
__device__ float g_mean[B_ * N_];
__device__ float g_istd[B_ * N_];
__device__ float g_std [B_ * N_];
__device__ float g_tok  [(size_t)MROWS * L_];
__device__ float g_enc  [(size_t)MROWS * D_];
__device__ float g_xz   [(size_t)MROWS * 128];      // [f(64) | b(64)] per row
__device__ float g_dtcat[(size_t)MROWS * 1024];     // [dt_f(512) | dt_b(512)]
__device__ float g_ycat [(size_t)MROWS * 2 * D_];   // [yf | yb]
__device__ float g_fused[(size_t)MROWS * D_];
__device__ float g_hbuf [(size_t)MROWS * D_];
__device__ float g_hn   [(size_t)MROWS * D_];
__device__ float g_pre  [(size_t)MROWS * PRED_];

// pre-split weights (hi,lo tf32 pairs)
__device__ float2 g_wembS [512 * 512];
__device__ float2 g_wxS   [512 * 128];
__device__ float2 g_wdtS  [128 * 1024];
__device__ float2 g_wzS   [1024 * 512];
__device__ float2 g_woS   [512 * 512];
__device__ float2 g_wprojS[512 * PRED_];
__device__ float  g_bdt   [1024];

// chunked-scan intermediates
__device__ float g_dts [2 * NC_ * B_ * D_];
__device__ float g_hfin[(size_t)2 * NC_ * B_ * S_ * D_];
__device__ float g_h0  [(size_t)2 * NC_ * B_ * S_ * D_];

// ---------------------------------------------------------------------------
// tf32 split helper
// ---------------------------------------------------------------------------
__device__ __forceinline__ float2 split_tf32_f2(float v)
{
    uint32_t h;
    asm("cvt.rna.tf32.f32 %0, %1;" : "=r"(h) : "f"(v));
    float r = v - __uint_as_float(h);
    uint32_t lw;
    asm("cvt.rna.tf32.f32 %0, %1;" : "=r"(lw) : "f"(r));
    return make_float2(__uint_as_float(h), __uint_as_float(lw));
}

// ---------------------------------------------------------------------------
// 0) pack + pre-split ALL weights into (hi,lo) tf32 pairs
// ---------------------------------------------------------------------------
namespace {
constexpr int SZ_EMB  = 512 * 512;
constexpr int SZ_WX   = 512 * 128;
constexpr int SZ_WDT  = 128 * 1024;
constexpr int SZ_WZ   = 1024 * 512;
constexpr int SZ_WO   = 512 * 512;
constexpr int SZ_WPJ  = 512 * PRED_;
constexpr int SZ_ALL  = SZ_EMB + SZ_WX + SZ_WDT + SZ_WZ + SZ_WO + SZ_WPJ + 1024;
}

__global__ void split_weights(const float* __restrict__ Wemb,
                              const float* __restrict__ Wxf,  const float* __restrict__ Wxb,
                              const float* __restrict__ Wdtf, const float* __restrict__ Wdtb,
                              const float* __restrict__ Wz,   const float* __restrict__ Wo,
                              const float* __restrict__ Wproj,
                              const float* __restrict__ bdtf, const float* __restrict__ bdtb)
{
    int i = blockIdx.x * 256 + threadIdx.x;
    if (i < SZ_EMB) { g_wembS[i] = split_tf32_f2(Wemb[i]); return; }
    i -= SZ_EMB;
    if (i < SZ_WX) {
        int r = i >> 7, c = i & 127;
        float v = (c < 64) ? Wxf[r * 64 + c] : Wxb[r * 64 + (c - 64)];
        g_wxS[i] = split_tf32_f2(v);
        return;
    }
    i -= SZ_WX;
    if (i < SZ_WDT) {
        int r = i >> 10, c = i & 1023;
        float v = 0.f;
        if (c < 512) { if (r < 32) v = Wdtf[r * 512 + c]; }
        else         { if (r >= 64 && r < 96) v = Wdtb[(r - 64) * 512 + (c - 512)]; }
        g_wdtS[i] = split_tf32_f2(v);
        return;
    }
    i -= SZ_WDT;
    if (i < SZ_WZ) { g_wzS[i] = split_tf32_f2(Wz[i]); return; }
    i -= SZ_WZ;
    if (i < SZ_WO) { g_woS[i] = split_tf32_f2(Wo[i]); return; }
    i -= SZ_WO;
    if (i < SZ_WPJ) { g_wprojS[i] = split_tf32_f2(Wproj[i]); return; }
    i -= SZ_WPJ;
    if (i < 1024) g_bdt[i] = (i < 512) ? bdtf[i] : bdtb[i - 512];
}

// ---------------------------------------------------------------------------
// 1) per-(b,n) mean / std over L
// ---------------------------------------------------------------------------
__global__ void stats_kernel(const float* __restrict__ x)
{
    __shared__ float sh1[8][32];
    __shared__ float sh2[8][32];
    const int b  = blockIdx.x;
    const int tx = threadIdx.x & 31;
    const int lg = threadIdx.x >> 5;
    const int n  = blockIdx.y * 32 + tx;

    float s = 0.f, s2 = 0.f;
    if (n < N_) {
        #pragma unroll 4
        for (int l = lg; l < L_; l += 8) {
            float v = x[((size_t)b * L_ + l) * N_ + n];
            s  += v;
            s2 += v * v;
        }
    }
    sh1[lg][tx] = s;
    sh2[lg][tx] = s2;
    __syncthreads();
    if (lg == 0 && n < N_) {
        float S1 = 0.f, S2 = 0.f;
        #pragma unroll
        for (int r = 0; r < 8; r++) { S1 += sh1[r][tx]; S2 += sh2[r][tx]; }
        float mu  = S1 / (float)L_;
        float var = S2 / (float)L_ - mu * mu;
        float sd  = sqrtf(var + 1e-5f);
        g_mean[b * N_ + n] = mu;
        g_std [b * N_ + n] = sd;
        g_istd[b * N_ + n] = 1.f / sd;
    }
}

// ---------------------------------------------------------------------------
// 2) tok build (tiled transpose + normalize)
// ---------------------------------------------------------------------------
__global__ void build_tok(const float* __restrict__ xe, const float* __restrict__ xm)
{
    __shared__ float tile[32][33];
    const int b  = blockIdx.z;
    const int tx = threadIdx.x, ty = threadIdx.y;
    const int t0 = blockIdx.x * 32;
    const int l0 = blockIdx.y * 32;

    #pragma unroll
    for (int j = 0; j < 4; j++) {
        int l = l0 + ty + 8 * j;
        int t = t0 + tx;
        float v = 0.f;
        if (t < T_) {
            if (t < N_) v = (xe[((size_t)b * L_ + l) * N_ + t] - g_mean[b * N_ + t]) * g_istd[b * N_ + t];
            else        v = xm[((size_t)b * L_ + l) * MK_ + (t - N_)];
        }
        tile[ty + 8 * j][tx] = v;
    }
    __syncthreads();
    #pragma unroll
    for (int j = 0; j < 4; j++) {
        int t = t0 + ty + 8 * j;
        int l = l0 + tx;
        if (t < T_) g_tok[((size_t)b * T_ + t) * L_ + l] = tile[tx][ty + 8 * j];
    }
}

// ---------------------------------------------------------------------------
// mma helper
// ---------------------------------------------------------------------------
__device__ __forceinline__ void mma_tf32(float* c, const uint32_t* a, uint32_t b0, uint32_t b1)
{
    asm volatile(
        "mma.sync.aligned.m16n8k8.row.col.f32.tf32.tf32.f32 "
        "{%0,%1,%2,%3},{%4,%5,%6,%7},{%8,%9},{%0,%1,%2,%3};\n"
        : "+f"(c[0]), "+f"(c[1]), "+f"(c[2]), "+f"(c[3])
        : "r"(a[0]), "r"(a[1]), "r"(a[2]), "r"(a[3]), "r"(b0), "r"(b1));
}

// ---------------------------------------------------------------------------
// Tensor-core GEMM, tf32 3x split.
// B arrives PRE-SPLIT from global (float2 hi/lo). A is split once at smem
// commit. Inner loop: pure LDS.64 + MMA. BM=64 BN=128 BK=32, 256 threads.
// Dynamic smem: As 64x36 float2 + Bs 32x132 float2 = 52224 B.
// ---------------------------------------------------------------------------
constexpr int EPI_NONE = 0, EPI_SOFTPLUS = 1, EPI_SIGFUSE = 2, EPI_ADD = 3;
constexpr int LDA2 = 36;    // float2 stride per A row:  banks (8g+2tg)%32 distinct/phase
constexpr int LDB2 = 132;   // float2 stride per B k-row: banks (8tg+2g)%32 distinct/phase
constexpr int GEMM_SMEM = (64 * LDA2 + 32 * LDB2) * (int)sizeof(float2);  // 52224

template<int EPI>
__global__ void __launch_bounds__(256)
gemm_tc(const float* __restrict__ A, int lda,
        const float2* __restrict__ Bm, int ldb,        // pre-split, ldb = element cols
        float* __restrict__ C, int ldc,
        int M, int Ncols, int K,
        const float* __restrict__ bias,
        const float* __restrict__ e1,
        const float* __restrict__ e2,
        int elds)
{
    constexpr int BM = 64, BN = 128, BK = 32;
    extern __shared__ float2 smem2[];
    float2* As = smem2;                 // BM * LDA2
    float2* Bs = smem2 + BM * LDA2;     // BK * LDB2

    const int tid = threadIdx.x;
    const int w   = tid >> 5, l = tid & 31;
    const int g   = l >> 2, tg = l & 3;
    const int wr  = w >> 2, wc = w & 3;      // 2 x 4 warp grid, 32x32 warp tiles
    const int m0w = wr * 32, n0w = wc * 32;
    const int rowBase = blockIdx.y * BM;
    const int colBase = blockIdx.x * BN;

    // A loader: 4 thr/row, float4 (4 fp32) each. 64 rows x 8 k-quads... (BK=32 -> 8 quads? 4 thr cover 16 elems? )
    // A tile 64x32 fp32 = 2048 = 256 thr * 8 -> each thread 2 float4
    const int arow = tid >> 2, akq = tid & 3;      // akq in 0..3, each float4 = 4 cols; x2 halves below

    float acc[2][4][4];
    #pragma unroll
    for (int mi = 0; mi < 2; mi++)
        #pragma unroll
        for (int ni = 0; ni < 4; ni++)
            #pragma unroll
            for (int q = 0; q < 4; q++) acc[mi][ni][q] = 0.f;

    float4 pa[2];   // A prefetch: 64x32 fp32 = 2048 = 256 thr * 8 fp32
    float4 pb[8];   // B prefetch: 32x128 float2 = 4096 f2 = 2048 float4 / 256 thr = 8

    // initial prefetch (k0 = 0)
    {
        int gr = rowBase + arow;
        #pragma unroll
        for (int h = 0; h < 2; h++) {
            pa[h] = make_float4(0.f, 0.f, 0.f, 0.f);
            if (gr < M) pa[h] = *reinterpret_cast<const float4*>(A + (size_t)gr * lda + (akq + 4 * h) * 4);
        }
        #pragma unroll
        for (int j = 0; j < 8; j++) {
            int idx  = tid + j * 256;
            int brow = idx >> 6, nc4 = idx & 63;
            int gc   = colBase + nc4 * 2;
            pb[j] = make_float4(0.f, 0.f, 0.f, 0.f);
            if (gc < Ncols) pb[j] = *reinterpret_cast<const float4*>(Bm + (size_t)brow * ldb + gc);
        }
    }

    for (int k0 = 0; k0 < K; k0 += BK) {
        // commit A (split once here) and B (already split)
        #pragma unroll
        for (int h = 0; h < 2; h++) {
            float2 s0 = split_tf32_f2(pa[h].x);
            float2 s1 = split_tf32_f2(pa[h].y);
            float2 s2 = split_tf32_f2(pa[h].z);
            float2 s3 = split_tf32_f2(pa[h].w);
            float2* ap = &As[arow * LDA2 + (akq + 4 * h) * 4];
            *reinterpret_cast<float4*>(ap)     = make_float4(s0.x, s0.y, s1.x, s1.y);
            *reinterpret_cast<float4*>(ap + 2) = make_float4(s2.x, s2.y, s3.x, s3.y);
        }
        #pragma unroll
        for (int j = 0; j < 8; j++) {
            int idx  = tid + j * 256;
            int brow = idx >> 6, nc4 = idx & 63;
            *reinterpret_cast<float4*>(&Bs[brow * LDB2 + nc4 * 2]) = pb[j];
        }
        __syncthreads();

        // prefetch next tile
        if (k0 + BK < K) {
            const int kn = k0 + BK;
            int gr = rowBase + arow;
            #pragma unroll
            for (int h = 0; h < 2; h++) {
                pa[h] = make_float4(0.f, 0.f, 0.f, 0.f);
                if (gr < M) pa[h] = *reinterpret_cast<const float4*>(A + (size_t)gr * lda + kn + (akq + 4 * h) * 4);
            }
            #pragma unroll
            for (int j = 0; j < 8; j++) {
                int idx  = tid + j * 256;
                int brow = idx >> 6, nc4 = idx & 63;
                int gc   = colBase + nc4 * 2;
                pb[j] = make_float4(0.f, 0.f, 0.f, 0.f);
                if (gc < Ncols) pb[j] = *reinterpret_cast<const float4*>(Bm + (size_t)(kn + brow) * ldb + gc);
            }
        }

        // compute 4 k-chunks of 8 — pure LDS.64 + MMA
        #pragma unroll
        for (int kc = 0; kc < 4; kc++) {
            const int kk = kc * 8;
            uint32_t ah[2][4], al[2][4];
            #pragma unroll
            for (int mi = 0; mi < 2; mi++) {
                const int r0 = m0w + mi * 16;
                float2 p0 = As[(r0 + g    ) * LDA2 + kk + tg    ];
                float2 p1 = As[(r0 + g + 8) * LDA2 + kk + tg    ];
                float2 p2 = As[(r0 + g    ) * LDA2 + kk + tg + 4];
                float2 p3 = As[(r0 + g + 8) * LDA2 + kk + tg + 4];
                ah[mi][0] = __float_as_uint(p0.x); al[mi][0] = __float_as_uint(p0.y);
                ah[mi][1] = __float_as_uint(p1.x); al[mi][1] = __float_as_uint(p1.y);
                ah[mi][2] = __float_as_uint(p2.x); al[mi][2] = __float_as_uint(p2.y);
                ah[mi][3] = __float_as_uint(p3.x); al[mi][3] = __float_as_uint(p3.y);
            }
            #pragma unroll
            for (int ni = 0; ni < 4; ni++) {
                const int ccol = n0w + ni * 8 + g;
                float2 q0 = Bs[(kk + tg    ) * LDB2 + ccol];
                float2 q1 = Bs[(kk + tg + 4) * LDB2 + ccol];
                uint32_t bh0 = __float_as_uint(q0.x), bl0 = __float_as_uint(q0.y);
                uint32_t bh1 = __float_as_uint(q1.x), bl1 = __float_as_uint(q1.y);
                #pragma unroll
                for (int mi = 0; mi < 2; mi++) {
                    mma_tf32(acc[mi][ni], ah[mi], bl0, bl1);
                    mma_tf32(acc[mi][ni], al[mi], bh0, bh1);
                    mma_tf32(acc[mi][ni], ah[mi], bh0, bh1);
                }
            }
        }
        __syncthreads();
    }

    // epilogue
    #pragma unroll
    for (int mi = 0; mi < 2; mi++) {
        #pragma unroll
        for (int half = 0; half < 2; half++) {
            int gr = rowBase + m0w + mi * 16 + g + half * 8;
            if (gr >= M) continue;
            #pragma unroll
            for (int ni = 0; ni < 4; ni++) {
                int gc = colBase + n0w + ni * 8 + 2 * tg;
                if (gc >= Ncols) continue;
                float x0 = acc[mi][ni][half * 2 + 0];
                float x1 = acc[mi][ni][half * 2 + 1];
                if (bias) { x0 += bias[gc]; x1 += bias[gc + 1]; }
                if (EPI == EPI_SOFTPLUS) {
                    x0 = (x0 > 15.f) ? x0 : log1pf(__expf(x0));
                    x1 = (x1 > 15.f) ? x1 : log1pf(__expf(x1));
                } else if (EPI == EPI_SIGFUSE) {
                    size_t ei = (size_t)gr * elds + gc;
                    float z0 = 1.f / (1.f + __expf(-x0));
                    float z1 = 1.f / (1.f + __expf(-x1));
                    x0 = z0 * e1[ei]     + (1.f - z0) * e2[ei];
                    x1 = z1 * e1[ei + 1] + (1.f - z1) * e2[ei + 1];
                } else if (EPI == EPI_ADD) {
                    size_t ei = (size_t)gr * elds + gc;
                    x0 += e1[ei];
                    x1 += e1[ei + 1];
                }
                C[(size_t)gr * ldc + gc]     = x0;
                C[(size_t)gr * ldc + gc + 1] = x1;
            }
        }
    }
}

// ---------------------------------------------------------------------------
// scan helpers
// ---------------------------------------------------------------------------
__device__ __forceinline__ void load_a(const float* __restrict__ AL, int d,
                                       float* a, float& a0, bool& structured)
{
    #pragma unroll
    for (int s = 0; s < S_; s++) a[s] = -expf(AL[d * S_ + s]);
    a0 = a[0];
    structured = true;
    #pragma unroll
    for (int s = 0; s < S_; s++) {
        float ideal = (float)(s + 1) * a0;
        if (fabsf(a[s] - ideal) > 1e-4f * fabsf(a[s])) structured = false;
    }
}

__device__ __forceinline__ void make_powers(float q, float* P)
{
    float q2 = q * q, q4 = q2 * q2, q8 = q4 * q4;
    P[0] = q;        P[1] = q2;       P[2] = q2 * q;    P[3] = q4;
    P[4] = q4 * q;   P[5] = q4 * q2;  P[6] = q4 * P[2]; P[7] = q8;
    P[8] = q8 * q;   P[9] = q8 * q2;  P[10]= q8 * P[2]; P[11]= q8 * q4;
    P[12]= q8 * P[4];P[13]= q8 * P[5];P[14]= q8 * P[6]; P[15]= q8 * q8;
}

__device__ __forceinline__ void calc_P(bool structured, float a0, const float* a,
                                       float x, float* P)
{
    if (structured) {
        make_powers(__expf(a0 * x), P);
    } else {
        #pragma unroll
        for (int s = 0; s < 16; s++) P[s] = __expf(a[s] * x);
    }
}

// Phase A: per-chunk scan from zero state; store final h and sum(dt)
__global__ void __launch_bounds__(128)
scan_partial(const float* __restrict__ Alogf, const float* __restrict__ Alogb)
{
    const int bx  = blockIdx.x;            // 52 = 4 dblocks * 13 chunks
    const int db  = bx & 3;
    const int c   = bx >> 2;
    const int d   = db * 128 + threadIdx.x;
    const int b   = blockIdx.y;
    const int dir = blockIdx.z;

    float a[S_], a0; bool structured;
    load_a(dir ? Alogb : Alogf, d, a, a0, structured);

    float h[S_];
    #pragma unroll
    for (int s = 0; s < S_; s++) h[s] = 0.f;
    float dts = 0.f;

    for (int t = c * CH_; t < c * CH_ + CH_; t++) {
        const int tt = dir ? (T_ - 1 - t) : t;
        const size_t rb = (size_t)b * T_ + tt;
        const float dtv = g_dtcat[rb * 1024 + dir * 512 + d];
        const float u   = g_enc[rb * D_ + d];
        const float du  = dtv * u;
        dts += dtv;

        const float4* v4 = reinterpret_cast<const float4*>(g_xz + rb * 128 + dir * 64 + 32);
        float4 B0 = v4[0], B1 = v4[1], B2 = v4[2], B3 = v4[3];
        float bc[16] = {B0.x,B0.y,B0.z,B0.w, B1.x,B1.y,B1.z,B1.w,
                        B2.x,B2.y,B2.z,B2.w, B3.x,B3.y,B3.z,B3.w};

        float P[16];
        calc_P(structured, a0, a, dtv, P);

        #pragma unroll
        for (int s = 0; s < 16; s++) h[s] = fmaf(P[s], h[s], du * bc[s]);
    }

    const size_t base = (size_t)(dir * NC_ + c) * B_ + b;
    g_dts[base * D_ + d] = dts;
    #pragma unroll
    for (int s = 0; s < S_; s++)
        g_hfin[(base * S_ + s) * D_ + d] = h[s];
}

// Phase B: sequential combine over chunks; store per-chunk initial states
__global__ void __launch_bounds__(256)
scan_combine(const float* __restrict__ Alogf, const float* __restrict__ Alogb)
{
    const int idx = blockIdx.x * 256 + threadIdx.x;   // 16384 total
    const int dir = idx >> 13;
    const int b   = (idx >> 9) & 15;
    const int d   = idx & 511;

    float a[S_], a0; bool structured;
    load_a(dir ? Alogb : Alogf, d, a, a0, structured);

    float h[S_];
    #pragma unroll
    for (int s = 0; s < S_; s++) h[s] = 0.f;

    for (int c = 0; c < NC_; c++) {
        const size_t base = (size_t)(dir * NC_ + c) * B_ + b;
        #pragma unroll
        for (int s = 0; s < S_; s++)
            g_h0[(base * S_ + s) * D_ + d] = h[s];
        const float dts = g_dts[base * D_ + d];
        float P[16];
        calc_P(structured, a0, a, dts, P);
        #pragma unroll
        for (int s = 0; s < S_; s++)
            h[s] = fmaf(P[s], h[s], g_hfin[(base * S_ + s) * D_ + d]);
    }
}

// Phase C: replay chunk from corrected initial state, write y
__global__ void __launch_bounds__(128)
scan_final(const float* __restrict__ Alogf, const float* __restrict__ Alogb,
           const float* __restrict__ Dskf,  const float* __restrict__ Dskb)
{
    const int bx  = blockIdx.x;
    const int db  = bx & 3;
    const int c   = bx >> 2;
    const int d   = db * 128 + threadIdx.x;
    const int b   = blockIdx.y;
    const int dir = blockIdx.z;

    float a[S_], a0; bool structured;
    load_a(dir ? Alogb : Alogf, d, a, a0, structured);
    const float Dsk = (dir ? Dskb : Dskf)[d];

    const size_t base = (size_t)(dir * NC_ + c) * B_ + b;
    float h[S_];
    #pragma unroll
    for (int s = 0; s < S_; s++)
        h[s] = g_h0[(base * S_ + s) * D_ + d];

    for (int t = c * CH_; t < c * CH_ + CH_; t++) {
        const int tt = dir ? (T_ - 1 - t) : t;
        const size_t rb = (size_t)b * T_ + tt;
        const float dtv = g_dtcat[rb * 1024 + dir * 512 + d];
        const float u   = g_enc[rb * D_ + d];
        const float du  = dtv * u;

        const float4* v4 = reinterpret_cast<const float4*>(g_xz + rb * 128 + dir * 64 + 32);
        float4 B0 = v4[0], B1 = v4[1], B2 = v4[2], B3 = v4[3];
        float4 C0 = v4[4], C1 = v4[5], C2 = v4[6], C3 = v4[7];
        float bc[16] = {B0.x,B0.y,B0.z,B0.w, B1.x,B1.y,B1.z,B1.w,
                        B2.x,B2.y,B2.z,B2.w, B3.x,B3.y,B3.z,B3.w};
        float cc[16] = {C0.x,C0.y,C0.z,C0.w, C1.x,C1.y,C1.z,C1.w,
                        C2.x,C2.y,C2.z,C2.w, C3.x,C3.y,C3.z,C3.w};

        float P[16];
        calc_P(structured, a0, a, dtv, P);

        float acc0 = 0.f, acc1 = 0.f, acc2 = 0.f, acc3 = 0.f;
        #pragma unroll
        for (int s = 0; s < 16; s += 4) {
            h[s+0] = fmaf(P[s+0], h[s+0], du * bc[s+0]);
            h[s+1] = fmaf(P[s+1], h[s+1], du * bc[s+1]);
            h[s+2] = fmaf(P[s+2], h[s+2], du * bc[s+2]);
            h[s+3] = fmaf(P[s+3], h[s+3], du * bc[s+3]);
            acc0 = fmaf(h[s+0], cc[s+0], acc0);
            acc1 = fmaf(h[s+1], cc[s+1], acc1);
            acc2 = fmaf(h[s+2], cc[s+2], acc2);
            acc3 = fmaf(h[s+3], cc[s+3], acc3);
        }
        g_ycat[rb * 1024 + dir * 512 + d] = (acc0 + acc1) + (acc2 + acc3) + u * Dsk;
    }
}

// ---------------------------------------------------------------------------
// LayerNorm over D
// ---------------------------------------------------------------------------
__global__ void ln_kernel(const float* __restrict__ gamma, const float* __restrict__ beta)
{
    __shared__ float r1[256];
    __shared__ float r2[256];
    __shared__ float mu_s, rs_s;
    const int row = blockIdx.x;
    const int tid = threadIdx.x;
    const float* hr = g_hbuf + (size_t)row * D_;
    float v0 = hr[tid], v1 = hr[tid + 256];
    r1[tid] = v0 + v1;
    r2[tid] = v0 * v0 + v1 * v1;
    __syncthreads();
    for (int off = 128; off > 0; off >>= 1) {
        if (tid < off) { r1[tid] += r1[tid + off]; r2[tid] += r2[tid + off]; }
        __syncthreads();
    }
    if (tid == 0) {
        float mu  = r1[0] / (float)D_;
        float var = r2[0] / (float)D_ - mu * mu;
        mu_s = mu;
        rs_s = rsqrtf(var + 1e-5f);
    }
    __syncthreads();
    float mu = mu_s, rs = rs_s;
    g_hn[(size_t)row * D_ + tid]       = (v0 - mu) * rs * gamma[tid]       + beta[tid];
    g_hn[(size_t)row * D_ + tid + 256] = (v1 - mu) * rs * gamma[tid + 256] + beta[tid + 256];
}

// ---------------------------------------------------------------------------
// output transpose + de-normalize
// ---------------------------------------------------------------------------
__global__ void out_kernel(float* __restrict__ out)
{
    int idx = blockIdx.x * 256 + threadIdx.x;
    if (idx >= B_ * PRED_ * N_) return;
    int n = idx % N_;
    int p = (idx / N_) % PRED_;
    int b = idx / (N_ * PRED_);
    float v = g_pre[((size_t)b * T_ + n) * PRED_ + p];
    out[idx] = v * g_std[b * N_ + n] + g_mean[b * N_ + n];
}

// ---------------------------------------------------------------------------
// launch
// ---------------------------------------------------------------------------
extern "C" void kernel_launch(void* const* d_in, const int* in_sizes, int n_in,
                              void* d_out, int out_size)
{
    const float* x_enc  = (const float*)d_in[0];
    const float* x_mark = (const float*)d_in[1];
    const float* W_emb  = (const float*)d_in[4];
    const float* b_emb  = (const float*)d_in[5];
    const float* Alogf  = (const float*)d_in[6];
    const float* Wx_f   = (const float*)d_in[7];
    const float* Wdt_f  = (const float*)d_in[8];
    const float* bdt_f  = (const float*)d_in[9];
    const float* Dsk_f  = (const float*)d_in[10];
    const float* Alogb  = (const float*)d_in[11];
    const float* Wx_b   = (const float*)d_in[12];
    const float* Wdt_b  = (const float*)d_in[13];
    const float* bdt_b  = (const float*)d_in[14];
    const float* Dsk_b  = (const float*)d_in[15];
    const float* Wz     = (const float*)d_in[16];
    const float* bz     = (const float*)d_in[17];
    const float* Wo     = (const float*)d_in[18];
    const float* bo     = (const float*)d_in[19];
    const float* lng    = (const float*)d_in[20];
    const float* lnb    = (const float*)d_in[21];
    const float* Wproj  = (const float*)d_in[22];
    const float* bproj  = (const float*)d_in[23];
    float* out = (float*)d_out;

    float *tok, *enc, *xz, *dtc, *ycat, *fused, *hb, *hn, *pre, *bdt;
    float2 *wembS, *wxS, *wdtS, *wzS, *woS, *wprojS;
    cudaGetSymbolAddress((void**)&tok,    g_tok);
    cudaGetSymbolAddress((void**)&enc,    g_enc);
    cudaGetSymbolAddress((void**)&xz,     g_xz);
    cudaGetSymbolAddress((void**)&dtc,    g_dtcat);
    cudaGetSymbolAddress((void**)&ycat,   g_ycat);
    cudaGetSymbolAddress((void**)&fused,  g_fused);
    cudaGetSymbolAddress((void**)&hb,     g_hbuf);
    cudaGetSymbolAddress((void**)&hn,     g_hn);
    cudaGetSymbolAddress((void**)&pre,    g_pre);
    cudaGetSymbolAddress((void**)&bdt,    g_bdt);
    cudaGetSymbolAddress((void**)&wembS,  g_wembS);
    cudaGetSymbolAddress((void**)&wxS,    g_wxS);
    cudaGetSymbolAddress((void**)&wdtS,   g_wdtS);
    cudaGetSymbolAddress((void**)&wzS,    g_wzS);
    cudaGetSymbolAddress((void**)&woS,    g_woS);
    cudaGetSymbolAddress((void**)&wprojS, g_wprojS);

    // allow 51 KB dynamic smem (idempotent)
    cudaFuncSetAttribute(gemm_tc<EPI_NONE>,     cudaFuncAttributeMaxDynamicSharedMemorySize, GEMM_SMEM);
    cudaFuncSetAttribute(gemm_tc<EPI_SOFTPLUS>, cudaFuncAttributeMaxDynamicSharedMemorySize, GEMM_SMEM);
    cudaFuncSetAttribute(gemm_tc<EPI_SIGFUSE>,  cudaFuncAttributeMaxDynamicSharedMemorySize, GEMM_SMEM);
    cudaFuncSetAttribute(gemm_tc<EPI_ADD>,      cudaFuncAttributeMaxDynamicSharedMemorySize, GEMM_SMEM);

    const int gy = (MROWS + 63) / 64;   // 82

    // 0) pre-split all weights
    split_weights<<<(SZ_ALL + 255) / 256, 256>>>(
        W_emb, Wx_f, Wx_b, Wdt_f, Wdt_b, Wz, Wo, Wproj, bdt_f, bdt_b);

    // 1) stats
    stats_kernel<<<dim3(B_, (N_ + 31) / 32), 256>>>(x_enc);

    // 2) tok
    build_tok<<<dim3((T_ + 31) / 32, L_ / 32, B_), dim3(32, 8)>>>(x_enc, x_mark);

    // 3) enc = tok @ W_emb + b_emb
    gemm_tc<EPI_NONE><<<dim3(D_ / 128, gy), 256, GEMM_SMEM>>>(
        tok, L_, wembS, D_, enc, D_, MROWS, D_, L_, b_emb, nullptr, nullptr, 0);

    // 4) xz = enc @ [Wx_f|Wx_b]
    gemm_tc<EPI_NONE><<<dim3(1, gy), 256, GEMM_SMEM>>>(
        enc, D_, wxS, 128, xz, 128, MROWS, 128, D_, nullptr, nullptr, nullptr, 0);

    // 5) dtcat = softplus(xz @ Wdt_blockdiag + bdt_cat)
    gemm_tc<EPI_SOFTPLUS><<<dim3(1024 / 128, gy), 256, GEMM_SMEM>>>(
        xz, 128, wdtS, 1024, dtc, 1024, MROWS, 1024, 128, bdt, nullptr, nullptr, 0);

    // 6) chunked bidirectional scan -> g_ycat
    scan_partial<<<dim3(4 * NC_, B_, 2), 128>>>(Alogf, Alogb);
    scan_combine<<<64, 256>>>(Alogf, Alogb);
    scan_final  <<<dim3(4 * NC_, B_, 2), 128>>>(Alogf, Alogb, Dsk_f, Dsk_b);

    // 7) fused = sigmoid(ycat @ Wz + bz) gating of yf/yb
    gemm_tc<EPI_SIGFUSE><<<dim3(D_ / 128, gy), 256, GEMM_SMEM>>>(
        ycat, 2 * D_, wzS, D_, fused, D_, MROWS, D_, 2 * D_, bz,
        ycat, ycat + D_, 2 * D_);

    // 8) h = enc + fused @ Wo + bo
    gemm_tc<EPI_ADD><<<dim3(D_ / 128, gy), 256, GEMM_SMEM>>>(
        fused, D_, woS, D_, hb, D_, MROWS, D_, D_, bo, enc, nullptr, D_);

    // 9) layernorm
    ln_kernel<<<MROWS, 256>>>(lng, lnb);

    // 10) pre = hn @ W_proj + b_proj
    gemm_tc<EPI_NONE><<<dim3(1, gy), 256, GEMM_SMEM>>>(
        hn, D_, wprojS, PRED_, pre, PRED_, MROWS, PRED_, D_, bproj, nullptr, nullptr, 0);

    // 11) output
    out_kernel<<<(B_ * PRED_ * N_ + 255) / 256, 256>>>(out);
}

// round 7
// speedup vs baseline: 1.3210x; 1.3210x over previous
#include <cuda_runtime.h>
#include <math.h>
#include <stdint.h>

// ---------------------------------------------------------------------------
// Problem dims
// ---------------------------------------------------------------------------
namespace {
constexpr int B_   = 16;
constexpr int L_   = 512;
constexpr int N_   = 321;
constexpr int MK_  = 4;
constexpr int D_   = 512;
constexpr int S_   = 16;
constexpr int DTR_ = 32;
constexpr int PRED_= 96;
constexpr int T_   = N_ + MK_;        // 325
constexpr int MROWS = B_ * T_;        // 5200
constexpr int NC_  = 13;              // scan chunks
constexpr int CH_  = 25;              // steps per chunk (13*25 = 325)
}

// ---------------------------------------------------------------------------
// Scratch
// ---------------------------------------------------------------------------
__device__ float g_mean[B_ * N_];
__device__ float g_istd[B_ * N_];
__device__ float g_std [B_ * N_];
__device__ float g_tok  [(size_t)MROWS * L_];
__device__ float g_enc  [(size_t)MROWS * D_];
__device__ float g_xz   [(size_t)MROWS * 128];      // [f(64) | b(64)] per row
__device__ float g_dtcat[(size_t)MROWS * 1024];     // [dt_f(512) | dt_b(512)]
__device__ float g_ycat [(size_t)MROWS * 2 * D_];   // [yf | yb]
__device__ float g_fused[(size_t)MROWS * D_];
__device__ float g_hbuf [(size_t)MROWS * D_];
__device__ float g_hn   [(size_t)MROWS * D_];
__device__ float g_pre  [(size_t)MROWS * PRED_];

// packed weights (fp32)
__device__ float g_wx [512 * 128];
__device__ float g_wdt[128 * 1024];
__device__ float g_bdt[1024];

// chunked-scan intermediates
__device__ float g_dts [2 * NC_ * B_ * D_];
__device__ float g_hfin[(size_t)2 * NC_ * B_ * S_ * D_];
__device__ float g_h0  [(size_t)2 * NC_ * B_ * S_ * D_];

// ---------------------------------------------------------------------------
// 0) pack weights
// ---------------------------------------------------------------------------
__global__ void pack_kernel(const float* __restrict__ Wxf, const float* __restrict__ Wxb,
                            const float* __restrict__ Wdtf, const float* __restrict__ Wdtb,
                            const float* __restrict__ bdtf, const float* __restrict__ bdtb)
{
    int i = blockIdx.x * 256 + threadIdx.x;
    if (i < 512 * 128) {
        int r = i >> 7, c = i & 127;
        g_wx[i] = (c < 64) ? Wxf[r * 64 + c] : Wxb[r * 64 + (c - 64)];
    }
    if (i < 128 * 1024) {
        int r = i >> 10, c = i & 1023;
        float v = 0.f;
        if (c < 512) { if (r < 32) v = Wdtf[r * 512 + c]; }
        else         { if (r >= 64 && r < 96) v = Wdtb[(r - 64) * 512 + (c - 512)]; }
        g_wdt[i] = v;
    }
    if (i < 1024) g_bdt[i] = (i < 512) ? bdtf[i] : bdtb[i - 512];
}

// ---------------------------------------------------------------------------
// 1) per-(b,n) mean / std over L
// ---------------------------------------------------------------------------
__global__ void stats_kernel(const float* __restrict__ x)
{
    __shared__ float sh1[8][32];
    __shared__ float sh2[8][32];
    const int b  = blockIdx.x;
    const int tx = threadIdx.x & 31;
    const int lg = threadIdx.x >> 5;
    const int n  = blockIdx.y * 32 + tx;

    float s = 0.f, s2 = 0.f;
    if (n < N_) {
        #pragma unroll 4
        for (int l = lg; l < L_; l += 8) {
            float v = x[((size_t)b * L_ + l) * N_ + n];
            s  += v;
            s2 += v * v;
        }
    }
    sh1[lg][tx] = s;
    sh2[lg][tx] = s2;
    __syncthreads();
    if (lg == 0 && n < N_) {
        float S1 = 0.f, S2 = 0.f;
        #pragma unroll
        for (int r = 0; r < 8; r++) { S1 += sh1[r][tx]; S2 += sh2[r][tx]; }
        float mu  = S1 / (float)L_;
        float var = S2 / (float)L_ - mu * mu;
        float sd  = sqrtf(var + 1e-5f);
        g_mean[b * N_ + n] = mu;
        g_std [b * N_ + n] = sd;
        g_istd[b * N_ + n] = 1.f / sd;
    }
}

// ---------------------------------------------------------------------------
// 2) tok build (tiled transpose + normalize)
// ---------------------------------------------------------------------------
__global__ void build_tok(const float* __restrict__ xe, const float* __restrict__ xm)
{
    __shared__ float tile[32][33];
    const int b  = blockIdx.z;
    const int tx = threadIdx.x, ty = threadIdx.y;
    const int t0 = blockIdx.x * 32;
    const int l0 = blockIdx.y * 32;

    #pragma unroll
    for (int j = 0; j < 4; j++) {
        int l = l0 + ty + 8 * j;
        int t = t0 + tx;
        float v = 0.f;
        if (t < T_) {
            if (t < N_) v = (xe[((size_t)b * L_ + l) * N_ + t] - g_mean[b * N_ + t]) * g_istd[b * N_ + t];
            else        v = xm[((size_t)b * L_ + l) * MK_ + (t - N_)];
        }
        tile[ty + 8 * j][tx] = v;
    }
    __syncthreads();
    #pragma unroll
    for (int j = 0; j < 4; j++) {
        int t = t0 + ty + 8 * j;
        int l = l0 + tx;
        if (t < T_) g_tok[((size_t)b * T_ + t) * L_ + l] = tile[tx][ty + 8 * j];
    }
}

// ---------------------------------------------------------------------------
// tf32 / mma / cp.async helpers
// ---------------------------------------------------------------------------
__device__ __forceinline__ void split_tf32(float v, uint32_t& hi, uint32_t& lo)
{
    uint32_t h;
    asm("cvt.rna.tf32.f32 %0, %1;" : "=r"(h) : "f"(v));
    float r = v - __uint_as_float(h);
    uint32_t lw;
    asm("cvt.rna.tf32.f32 %0, %1;" : "=r"(lw) : "f"(r));
    hi = h; lo = lw;
}

__device__ __forceinline__ void mma_tf32(float* c, const uint32_t* a, uint32_t b0, uint32_t b1)
{
    asm volatile(
        "mma.sync.aligned.m16n8k8.row.col.f32.tf32.tf32.f32 "
        "{%0,%1,%2,%3},{%4,%5,%6,%7},{%8,%9},{%0,%1,%2,%3};\n"
        : "+f"(c[0]), "+f"(c[1]), "+f"(c[2]), "+f"(c[3])
        : "r"(a[0]), "r"(a[1]), "r"(a[2]), "r"(a[3]), "r"(b0), "r"(b1));
}

__device__ __forceinline__ void cp_async16(float* smem_dst, const float* gsrc, int src_bytes)
{
    uint32_t saddr = (uint32_t)__cvta_generic_to_shared(smem_dst);
    asm volatile("cp.async.cg.shared.global [%0], [%1], 16, %2;\n"
                 :: "r"(saddr), "l"(gsrc), "r"(src_bytes));
}
__device__ __forceinline__ void cp_commit() { asm volatile("cp.async.commit_group;\n"); }
template<int NN>
__device__ __forceinline__ void cp_wait() { asm volatile("cp.async.wait_group %0;\n" :: "n"(NN)); }

// ---------------------------------------------------------------------------
// Tensor-core GEMM, tf32 3x split (R4 inner loop) + cp.async double buffering.
// BM=64 BN=128 BK=32, 256 threads (8 warps, 2x4 grid, 32x32 warp tiles).
// Dynamic smem: 2 stages x (As 64x36 + Bs 32x136) floats = 53248 B.
// ---------------------------------------------------------------------------
constexpr int EPI_NONE = 0, EPI_SOFTPLUS = 1, EPI_SIGFUSE = 2, EPI_ADD = 3;
constexpr int LDA_S = 36;
constexpr int LDB_S = 136;
constexpr int STG_F = 64 * LDA_S + 32 * LDB_S;            // floats per stage = 6656
constexpr int GEMM_SMEM = 2 * STG_F * (int)sizeof(float); // 53248

template<int EPI>
__global__ void __launch_bounds__(256, 3)
gemm_tc(const float* __restrict__ A, int lda,
        const float* __restrict__ Bm, int ldb,
        float* __restrict__ C, int ldc,
        int M, int Ncols, int K,
        const float* __restrict__ bias,
        const float* __restrict__ e1,
        const float* __restrict__ e2,
        int elds)
{
    constexpr int BM = 64, BN = 128, BK = 32;
    extern __shared__ float sm[];

    const int tid = threadIdx.x;
    const int w   = tid >> 5, l = tid & 31;
    const int g   = l >> 2, tg = l & 3;
    const int wr  = w >> 2, wc = w & 3;
    const int m0w = wr * 32, n0w = wc * 32;
    const int rowBase = blockIdx.y * BM;
    const int colBase = blockIdx.x * BN;

    // loader coords
    const int arow = tid >> 2, akq = tid & 3;      // A: 64 rows, quads akq & akq+4
    const int agr  = rowBase + arow;
    const int asz  = (agr < M) ? 16 : 0;
    const int agrc = (agr < M) ? agr : (M - 1);    // clamped address

    float acc[2][4][4];
    #pragma unroll
    for (int mi = 0; mi < 2; mi++)
        #pragma unroll
        for (int ni = 0; ni < 4; ni++)
            #pragma unroll
            for (int q = 0; q < 4; q++) acc[mi][ni][q] = 0.f;

    const int KT = K / BK;

    // tile loader (cp.async, zero-fill OOB)
    auto load_tile = [&](int kt, int stage) {
        float* As = sm + stage * STG_F;
        float* Bs = As + 64 * LDA_S;
        const int k0 = kt * BK;
        // A: 64x32, each thread two 16B chunks
        const float* ga = A + (size_t)agrc * lda + k0 + akq * 4;
        cp_async16(As + arow * LDA_S + akq * 4,       ga,      asz);
        cp_async16(As + arow * LDA_S + (akq + 4) * 4, ga + 16, asz);
        // B: 32x128, each thread four 16B chunks
        #pragma unroll
        for (int j = 0; j < 4; j++) {
            int idx  = tid + j * 256;
            int brow = idx >> 5, nq = idx & 31;
            int gc   = colBase + nq * 4;
            int bsz  = (gc < Ncols) ? 16 : 0;
            int gcc  = (gc < Ncols) ? gc : 0;
            cp_async16(Bs + brow * LDB_S + nq * 4,
                       Bm + (size_t)(k0 + brow) * ldb + gcc, bsz);
        }
    };

    // prologue
    load_tile(0, 0);
    cp_commit();
    if (KT > 1) { load_tile(1, 1); cp_commit(); }

    for (int kt = 0; kt < KT; kt++) {
        const int p = kt & 1;
        if (kt + 1 < KT) cp_wait<1>(); else cp_wait<0>();
        __syncthreads();

        const float* As = sm + p * STG_F;
        const float* Bs = As + 64 * LDA_S;

        #pragma unroll
        for (int kc = 0; kc < 4; kc++) {
            const int kk = kc * 8;
            uint32_t ah[2][4], al[2][4];
            #pragma unroll
            for (int mi = 0; mi < 2; mi++) {
                const int r0 = m0w + mi * 16;
                float v0 = As[(r0 + g    ) * LDA_S + kk + tg    ];
                float v1 = As[(r0 + g + 8) * LDA_S + kk + tg    ];
                float v2 = As[(r0 + g    ) * LDA_S + kk + tg + 4];
                float v3 = As[(r0 + g + 8) * LDA_S + kk + tg + 4];
                split_tf32(v0, ah[mi][0], al[mi][0]);
                split_tf32(v1, ah[mi][1], al[mi][1]);
                split_tf32(v2, ah[mi][2], al[mi][2]);
                split_tf32(v3, ah[mi][3], al[mi][3]);
            }
            #pragma unroll
            for (int ni = 0; ni < 4; ni++) {
                const int ccol = n0w + ni * 8 + g;
                float bv0 = Bs[(kk + tg    ) * LDB_S + ccol];
                float bv1 = Bs[(kk + tg + 4) * LDB_S + ccol];
                uint32_t bh0, bl0, bh1, bl1;
                split_tf32(bv0, bh0, bl0);
                split_tf32(bv1, bh1, bl1);
                #pragma unroll
                for (int mi = 0; mi < 2; mi++) {
                    mma_tf32(acc[mi][ni], ah[mi], bl0, bl1);
                    mma_tf32(acc[mi][ni], al[mi], bh0, bh1);
                    mma_tf32(acc[mi][ni], ah[mi], bh0, bh1);
                }
            }
        }
        __syncthreads();

        if (kt + 2 < KT) { load_tile(kt + 2, p); cp_commit(); }
    }

    // epilogue
    #pragma unroll
    for (int mi = 0; mi < 2; mi++) {
        #pragma unroll
        for (int half = 0; half < 2; half++) {
            int gr = rowBase + m0w + mi * 16 + g + half * 8;
            if (gr >= M) continue;
            #pragma unroll
            for (int ni = 0; ni < 4; ni++) {
                int gc = colBase + n0w + ni * 8 + 2 * tg;
                if (gc >= Ncols) continue;
                float x0 = acc[mi][ni][half * 2 + 0];
                float x1 = acc[mi][ni][half * 2 + 1];
                if (bias) { x0 += bias[gc]; x1 += bias[gc + 1]; }
                if (EPI == EPI_SOFTPLUS) {
                    x0 = (x0 > 15.f) ? x0 : log1pf(__expf(x0));
                    x1 = (x1 > 15.f) ? x1 : log1pf(__expf(x1));
                } else if (EPI == EPI_SIGFUSE) {
                    size_t ei = (size_t)gr * elds + gc;
                    float z0 = 1.f / (1.f + __expf(-x0));
                    float z1 = 1.f / (1.f + __expf(-x1));
                    x0 = z0 * e1[ei]     + (1.f - z0) * e2[ei];
                    x1 = z1 * e1[ei + 1] + (1.f - z1) * e2[ei + 1];
                } else if (EPI == EPI_ADD) {
                    size_t ei = (size_t)gr * elds + gc;
                    x0 += e1[ei];
                    x1 += e1[ei + 1];
                }
                C[(size_t)gr * ldc + gc]     = x0;
                C[(size_t)gr * ldc + gc + 1] = x1;
            }
        }
    }
}

// ---------------------------------------------------------------------------
// scan helpers
// ---------------------------------------------------------------------------
__device__ __forceinline__ void load_a(const float* __restrict__ AL, int d,
                                       float* a, float& a0, bool& structured)
{
    #pragma unroll
    for (int s = 0; s < S_; s++) a[s] = -expf(AL[d * S_ + s]);
    a0 = a[0];
    structured = true;
    #pragma unroll
    for (int s = 0; s < S_; s++) {
        float ideal = (float)(s + 1) * a0;
        if (fabsf(a[s] - ideal) > 1e-4f * fabsf(a[s])) structured = false;
    }
}

__device__ __forceinline__ void make_powers(float q, float* P)
{
    float q2 = q * q, q4 = q2 * q2, q8 = q4 * q4;
    P[0] = q;        P[1] = q2;       P[2] = q2 * q;    P[3] = q4;
    P[4] = q4 * q;   P[5] = q4 * q2;  P[6] = q4 * P[2]; P[7] = q8;
    P[8] = q8 * q;   P[9] = q8 * q2;  P[10]= q8 * P[2]; P[11]= q8 * q4;
    P[12]= q8 * P[4];P[13]= q8 * P[5];P[14]= q8 * P[6]; P[15]= q8 * q8;
}

__device__ __forceinline__ void calc_P(bool structured, float a0, const float* a,
                                       float x, float* P)
{
    if (structured) {
        make_powers(__expf(a0 * x), P);
    } else {
        #pragma unroll
        for (int s = 0; s < 16; s++) P[s] = __expf(a[s] * x);
    }
}

// Phase A: per-chunk scan from zero state; store final h and sum(dt)
__global__ void __launch_bounds__(128)
scan_partial(const float* __restrict__ Alogf, const float* __restrict__ Alogb)
{
    const int bx  = blockIdx.x;
    const int db  = bx & 3;
    const int c   = bx >> 2;
    const int d   = db * 128 + threadIdx.x;
    const int b   = blockIdx.y;
    const int dir = blockIdx.z;

    float a[S_], a0; bool structured;
    load_a(dir ? Alogb : Alogf, d, a, a0, structured);

    float h[S_];
    #pragma unroll
    for (int s = 0; s < S_; s++) h[s] = 0.f;
    float dts = 0.f;

    for (int t = c * CH_; t < c * CH_ + CH_; t++) {
        const int tt = dir ? (T_ - 1 - t) : t;
        const size_t rb = (size_t)b * T_ + tt;
        const float dtv = g_dtcat[rb * 1024 + dir * 512 + d];
        const float u   = g_enc[rb * D_ + d];
        const float du  = dtv * u;
        dts += dtv;

        const float4* v4 = reinterpret_cast<const float4*>(g_xz + rb * 128 + dir * 64 + 32);
        float4 B0 = v4[0], B1 = v4[1], B2 = v4[2], B3 = v4[3];
        float bc[16] = {B0.x,B0.y,B0.z,B0.w, B1.x,B1.y,B1.z,B1.w,
                        B2.x,B2.y,B2.z,B2.w, B3.x,B3.y,B3.z,B3.w};

        float P[16];
        calc_P(structured, a0, a, dtv, P);

        #pragma unroll
        for (int s = 0; s < 16; s++) h[s] = fmaf(P[s], h[s], du * bc[s]);
    }

    const size_t base = (size_t)(dir * NC_ + c) * B_ + b;
    g_dts[base * D_ + d] = dts;
    #pragma unroll
    for (int s = 0; s < S_; s++)
        g_hfin[(base * S_ + s) * D_ + d] = h[s];
}

// Phase B: sequential combine over chunks; store per-chunk initial states
__global__ void __launch_bounds__(256)
scan_combine(const float* __restrict__ Alogf, const float* __restrict__ Alogb)
{
    const int idx = blockIdx.x * 256 + threadIdx.x;
    const int dir = idx >> 13;
    const int b   = (idx >> 9) & 15;
    const int d   = idx & 511;

    float a[S_], a0; bool structured;
    load_a(dir ? Alogb : Alogf, d, a, a0, structured);

    float h[S_];
    #pragma unroll
    for (int s = 0; s < S_; s++) h[s] = 0.f;

    for (int c = 0; c < NC_; c++) {
        const size_t base = (size_t)(dir * NC_ + c) * B_ + b;
        #pragma unroll
        for (int s = 0; s < S_; s++)
            g_h0[(base * S_ + s) * D_ + d] = h[s];
        const float dts = g_dts[base * D_ + d];
        float P[16];
        calc_P(structured, a0, a, dts, P);
        #pragma unroll
        for (int s = 0; s < S_; s++)
            h[s] = fmaf(P[s], h[s], g_hfin[(base * S_ + s) * D_ + d]);
    }
}

// Phase C: replay chunk from corrected initial state, write y
__global__ void __launch_bounds__(128)
scan_final(const float* __restrict__ Alogf, const float* __restrict__ Alogb,
           const float* __restrict__ Dskf,  const float* __restrict__ Dskb)
{
    const int bx  = blockIdx.x;
    const int db  = bx & 3;
    const int c   = bx >> 2;
    const int d   = db * 128 + threadIdx.x;
    const int b   = blockIdx.y;
    const int dir = blockIdx.z;

    float a[S_], a0; bool structured;
    load_a(dir ? Alogb : Alogf, d, a, a0, structured);
    const float Dsk = (dir ? Dskb : Dskf)[d];

    const size_t base = (size_t)(dir * NC_ + c) * B_ + b;
    float h[S_];
    #pragma unroll
    for (int s = 0; s < S_; s++)
        h[s] = g_h0[(base * S_ + s) * D_ + d];

    for (int t = c * CH_; t < c * CH_ + CH_; t++) {
        const int tt = dir ? (T_ - 1 - t) : t;
        const size_t rb = (size_t)b * T_ + tt;
        const float dtv = g_dtcat[rb * 1024 + dir * 512 + d];
        const float u   = g_enc[rb * D_ + d];
        const float du  = dtv * u;

        const float4* v4 = reinterpret_cast<const float4*>(g_xz + rb * 128 + dir * 64 + 32);
        float4 B0 = v4[0], B1 = v4[1], B2 = v4[2], B3 = v4[3];
        float4 C0 = v4[4], C1 = v4[5], C2 = v4[6], C3 = v4[7];
        float bc[16] = {B0.x,B0.y,B0.z,B0.w, B1.x,B1.y,B1.z,B1.w,
                        B2.x,B2.y,B2.z,B2.w, B3.x,B3.y,B3.z,B3.w};
        float cc[16] = {C0.x,C0.y,C0.z,C0.w, C1.x,C1.y,C1.z,C1.w,
                        C2.x,C2.y,C2.z,C2.w, C3.x,C3.y,C3.z,C3.w};

        float P[16];
        calc_P(structured, a0, a, dtv, P);

        float acc0 = 0.f, acc1 = 0.f, acc2 = 0.f, acc3 = 0.f;
        #pragma unroll
        for (int s = 0; s < 16; s += 4) {
            h[s+0] = fmaf(P[s+0], h[s+0], du * bc[s+0]);
            h[s+1] = fmaf(P[s+1], h[s+1], du * bc[s+1]);
            h[s+2] = fmaf(P[s+2], h[s+2], du * bc[s+2]);
            h[s+3] = fmaf(P[s+3], h[s+3], du * bc[s+3]);
            acc0 = fmaf(h[s+0], cc[s+0], acc0);
            acc1 = fmaf(h[s+1], cc[s+1], acc1);
            acc2 = fmaf(h[s+2], cc[s+2], acc2);
            acc3 = fmaf(h[s+3], cc[s+3], acc3);
        }
        g_ycat[rb * 1024 + dir * 512 + d] = (acc0 + acc1) + (acc2 + acc3) + u * Dsk;
    }
}

// ---------------------------------------------------------------------------
// LayerNorm over D
// ---------------------------------------------------------------------------
__global__ void ln_kernel(const float* __restrict__ gamma, const float* __restrict__ beta)
{
    __shared__ float r1[256];
    __shared__ float r2[256];
    __shared__ float mu_s, rs_s;
    const int row = blockIdx.x;
    const int tid = threadIdx.x;
    const float* hr = g_hbuf + (size_t)row * D_;
    float v0 = hr[tid], v1 = hr[tid + 256];
    r1[tid] = v0 + v1;
    r2[tid] = v0 * v0 + v1 * v1;
    __syncthreads();
    for (int off = 128; off > 0; off >>= 1) {
        if (tid < off) { r1[tid] += r1[tid + off]; r2[tid] += r2[tid + off]; }
        __syncthreads();
    }
    if (tid == 0) {
        float mu  = r1[0] / (float)D_;
        float var = r2[0] / (float)D_ - mu * mu;
        mu_s = mu;
        rs_s = rsqrtf(var + 1e-5f);
    }
    __syncthreads();
    float mu = mu_s, rs = rs_s;
    g_hn[(size_t)row * D_ + tid]       = (v0 - mu) * rs * gamma[tid]       + beta[tid];
    g_hn[(size_t)row * D_ + tid + 256] = (v1 - mu) * rs * gamma[tid + 256] + beta[tid + 256];
}

// ---------------------------------------------------------------------------
// output transpose + de-normalize
// ---------------------------------------------------------------------------
__global__ void out_kernel(float* __restrict__ out)
{
    int idx = blockIdx.x * 256 + threadIdx.x;
    if (idx >= B_ * PRED_ * N_) return;
    int n = idx % N_;
    int p = (idx / N_) % PRED_;
    int b = idx / (N_ * PRED_);
    float v = g_pre[((size_t)b * T_ + n) * PRED_ + p];
    out[idx] = v * g_std[b * N_ + n] + g_mean[b * N_ + n];
}

// ---------------------------------------------------------------------------
// launch
// ---------------------------------------------------------------------------
extern "C" void kernel_launch(void* const* d_in, const int* in_sizes, int n_in,
                              void* d_out, int out_size)
{
    const float* x_enc  = (const float*)d_in[0];
    const float* x_mark = (const float*)d_in[1];
    const float* W_emb  = (const float*)d_in[4];
    const float* b_emb  = (const float*)d_in[5];
    const float* Alogf  = (const float*)d_in[6];
    const float* Wx_f   = (const float*)d_in[7];
    const float* Wdt_f  = (const float*)d_in[8];
    const float* bdt_f  = (const float*)d_in[9];
    const float* Dsk_f  = (const float*)d_in[10];
    const float* Alogb  = (const float*)d_in[11];
    const float* Wx_b   = (const float*)d_in[12];
    const float* Wdt_b  = (const float*)d_in[13];
    const float* bdt_b  = (const float*)d_in[14];
    const float* Dsk_b  = (const float*)d_in[15];
    const float* Wz     = (const float*)d_in[16];
    const float* bz     = (const float*)d_in[17];
    const float* Wo     = (const float*)d_in[18];
    const float* bo     = (const float*)d_in[19];
    const float* lng    = (const float*)d_in[20];
    const float* lnb    = (const float*)d_in[21];
    const float* Wproj  = (const float*)d_in[22];
    const float* bproj  = (const float*)d_in[23];
    float* out = (float*)d_out;

    float *tok, *enc, *xz, *dtc, *ycat, *fused, *hb, *hn, *pre, *wx, *wdt, *bdt;
    cudaGetSymbolAddress((void**)&tok,   g_tok);
    cudaGetSymbolAddress((void**)&enc,   g_enc);
    cudaGetSymbolAddress((void**)&xz,    g_xz);
    cudaGetSymbolAddress((void**)&dtc,   g_dtcat);
    cudaGetSymbolAddress((void**)&ycat,  g_ycat);
    cudaGetSymbolAddress((void**)&fused, g_fused);
    cudaGetSymbolAddress((void**)&hb,    g_hbuf);
    cudaGetSymbolAddress((void**)&hn,    g_hn);
    cudaGetSymbolAddress((void**)&pre,   g_pre);
    cudaGetSymbolAddress((void**)&wx,    g_wx);
    cudaGetSymbolAddress((void**)&wdt,   g_wdt);
    cudaGetSymbolAddress((void**)&bdt,   g_bdt);

    cudaFuncSetAttribute(gemm_tc<EPI_NONE>,     cudaFuncAttributeMaxDynamicSharedMemorySize, GEMM_SMEM);
    cudaFuncSetAttribute(gemm_tc<EPI_SOFTPLUS>, cudaFuncAttributeMaxDynamicSharedMemorySize, GEMM_SMEM);
    cudaFuncSetAttribute(gemm_tc<EPI_SIGFUSE>,  cudaFuncAttributeMaxDynamicSharedMemorySize, GEMM_SMEM);
    cudaFuncSetAttribute(gemm_tc<EPI_ADD>,      cudaFuncAttributeMaxDynamicSharedMemorySize, GEMM_SMEM);

    const int gy = (MROWS + 63) / 64;   // 82

    // 0) pack weights
    pack_kernel<<<512, 256>>>(Wx_f, Wx_b, Wdt_f, Wdt_b, bdt_f, bdt_b);

    // 1) stats
    stats_kernel<<<dim3(B_, (N_ + 31) / 32), 256>>>(x_enc);

    // 2) tok
    build_tok<<<dim3((T_ + 31) / 32, L_ / 32, B_), dim3(32, 8)>>>(x_enc, x_mark);

    // 3) enc = tok @ W_emb + b_emb
    gemm_tc<EPI_NONE><<<dim3(D_ / 128, gy), 256, GEMM_SMEM>>>(
        tok, L_, W_emb, D_, enc, D_, MROWS, D_, L_, b_emb, nullptr, nullptr, 0);

    // 4) xz = enc @ [Wx_f|Wx_b]
    gemm_tc<EPI_NONE><<<dim3(1, gy), 256, GEMM_SMEM>>>(
        enc, D_, wx, 128, xz, 128, MROWS, 128, D_, nullptr, nullptr, nullptr, 0);

    // 5) dtcat = softplus(xz @ Wdt_blockdiag + bdt_cat)
    gemm_tc<EPI_SOFTPLUS><<<dim3(1024 / 128, gy), 256, GEMM_SMEM>>>(
        xz, 128, wdt, 1024, dtc, 1024, MROWS, 1024, 128, bdt, nullptr, nullptr, 0);

    // 6) chunked bidirectional scan -> g_ycat
    scan_partial<<<dim3(4 * NC_, B_, 2), 128>>>(Alogf, Alogb);
    scan_combine<<<64, 256>>>(Alogf, Alogb);
    scan_final  <<<dim3(4 * NC_, B_, 2), 128>>>(Alogf, Alogb, Dsk_f, Dsk_b);

    // 7) fused = sigmoid(ycat @ Wz + bz) gating of yf/yb
    gemm_tc<EPI_SIGFUSE><<<dim3(D_ / 128, gy), 256, GEMM_SMEM>>>(
        ycat, 2 * D_, Wz, D_, fused, D_, MROWS, D_, 2 * D_, bz,
        ycat, ycat + D_, 2 * D_);

    // 8) h = enc + fused @ Wo + bo
    gemm_tc<EPI_ADD><<<dim3(D_ / 128, gy), 256, GEMM_SMEM>>>(
        fused, D_, Wo, D_, hb, D_, MROWS, D_, D_, bo, enc, nullptr, D_);

    // 9) layernorm
    ln_kernel<<<MROWS, 256>>>(lng, lnb);

    // 10) pre = hn @ W_proj + b_proj
    gemm_tc<EPI_NONE><<<dim3(1, gy), 256, GEMM_SMEM>>>(
        hn, D_, Wproj, PRED_, pre, PRED_, MROWS, PRED_, D_, bproj, nullptr, nullptr, 0);

    // 11) output
    out_kernel<<<(B_ * PRED_ * N_ + 255) / 256, 256>>>(out);
}